// round 1
// baseline (speedup 1.0000x reference)
#include <cuda_runtime.h>
#include <cuda_bf16.h>
#include <math_constants.h>

#define N_NODES 100000
#define N_EDGES 1600000
#define IN_F    128
#define HEADS   4
#define OUT_F   16
#define HF      (HEADS * OUT_F)      // 64
#define NEG_SLOPE 0.2f

// Scratch (static device allocations are allowed; cudaMalloc is not)
__device__ float g_z[N_NODES * HF];        // 25.6 MB
__device__ float g_el[N_NODES * HEADS];
__device__ float g_er[N_NODES * HEADS];
__device__ float g_m[N_NODES * HEADS];
__device__ float g_denom[N_NODES * HEADS];
__device__ float g_ex[N_EDGES * HEADS];    // 25.6 MB

// ---------------------------------------------------------------------------
// Kernel 0: init out=bias, m=-inf, denom=0
// ---------------------------------------------------------------------------
__global__ void k_init(float* __restrict__ out, const float* __restrict__ bias) {
    int idx = blockIdx.x * blockDim.x + threadIdx.x;
    int total_out = N_NODES * HF;
    int total_nh  = N_NODES * HEADS;
    if (idx < total_out) {
        out[idx] = bias[idx & (HF - 1)];
    }
    if (idx < total_nh) {
        g_m[idx] = -CUDART_INF_F;
        g_denom[idx] = 0.0f;
    }
}

// ---------------------------------------------------------------------------
// Kernel 1: z = feats @ W^T  (and el/er = <z, attn_l/r> per head)
// Block: 256 threads, 4 nodes/block. W staged in padded smem.
// ---------------------------------------------------------------------------
__global__ void k_gemm(const float* __restrict__ feats,
                       const float* __restrict__ W,
                       const float* __restrict__ attn_l,
                       const float* __restrict__ attn_r) {
    __shared__ float Wsm[IN_F][HF + 1];   // [k][col], padded: 33.3 KB
    __shared__ float fsm[4][IN_F];        // 4 node rows

    int tid = threadIdx.x;

    // Load W: W[col][k] row-major -> Wsm[k][col]
    for (int i = tid; i < HF * IN_F; i += 256) {
        int col = i >> 7;       // /128
        int k   = i & (IN_F - 1);
        Wsm[k][col] = W[i];
    }
    // Load 4 feature rows (coalesced)
    int base_node = blockIdx.x * 4;
    for (int i = tid; i < 4 * IN_F; i += 256) {
        int nl = i >> 7;
        int k  = i & (IN_F - 1);
        fsm[nl][k] = feats[(base_node + nl) * IN_F + k];
    }
    __syncthreads();

    int nl   = tid >> 6;        // local node 0..3
    int col  = tid & (HF - 1);  // 0..63
    int node = base_node + nl;
    if (node >= N_NODES) return;

    float acc = 0.0f;
#pragma unroll
    for (int k = 0; k < IN_F; k++) {
        acc = fmaf(fsm[nl][k], Wsm[k][col], acc);
    }
    g_z[node * HF + col] = acc;

    // el/er: reduce acc*attn over the 16 lanes of each head segment
    int h = col >> 4;           // head
    int f = col & 15;
    float vl = acc * attn_l[col];
    float vr = acc * attn_r[col];
#pragma unroll
    for (int off = 8; off >= 1; off >>= 1) {
        vl += __shfl_down_sync(0xffffffffu, vl, off, 16);
        vr += __shfl_down_sync(0xffffffffu, vr, off, 16);
    }
    if (f == 0) {
        g_el[node * HEADS + h] = vl;
        g_er[node * HEADS + h] = vr;
    }
}

// ---------------------------------------------------------------------------
// float atomicMax via int/uint monotonic mapping
// ---------------------------------------------------------------------------
__device__ __forceinline__ void atomicMaxFloat(float* addr, float value) {
    if (value >= 0.0f)
        atomicMax((int*)addr, __float_as_int(value));
    else
        atomicMin((unsigned int*)addr, __float_as_uint(value));
}

__device__ __forceinline__ float leaky_relu(float x) {
    return x > 0.0f ? x : NEG_SLOPE * x;
}

// ---------------------------------------------------------------------------
// Kernel 2: per-edge per-head attention logit -> segment max into g_m[dst]
// ---------------------------------------------------------------------------
__global__ void k_edge_max(const int* __restrict__ src, const int* __restrict__ dst) {
    int idx = blockIdx.x * blockDim.x + threadIdx.x;
    if (idx >= N_EDGES * HEADS) return;
    int e = idx >> 2;
    int h = idx & 3;
    int s = src[e];
    int d = dst[e];
    float v = leaky_relu(g_el[s * HEADS + h] + g_er[d * HEADS + h]);
    atomicMaxFloat(&g_m[d * HEADS + h], v);
}

// ---------------------------------------------------------------------------
// Kernel 3: ex = exp(e - m[dst]); scratch store + denom accumulation
// ---------------------------------------------------------------------------
__global__ void k_edge_exp(const int* __restrict__ src, const int* __restrict__ dst) {
    int idx = blockIdx.x * blockDim.x + threadIdx.x;
    if (idx >= N_EDGES * HEADS) return;
    int e = idx >> 2;
    int h = idx & 3;
    int s = src[e];
    int d = dst[e];
    float v = leaky_relu(g_el[s * HEADS + h] + g_er[d * HEADS + h]);
    float ex = __expf(v - g_m[d * HEADS + h]);
    g_ex[idx] = ex;
    atomicAdd(&g_denom[d * HEADS + h], ex);
}

// ---------------------------------------------------------------------------
// Kernel 4: out[dst] += alpha * z[src]   (vector red.global.add.v4.f32)
// One thread per (edge, 4-float chunk): 16 threads/edge.
// ---------------------------------------------------------------------------
__global__ void k_aggregate(const int* __restrict__ src, const int* __restrict__ dst,
                            float* __restrict__ out) {
    long long idx = (long long)blockIdx.x * blockDim.x + threadIdx.x;
    if (idx >= (long long)N_EDGES * 16) return;
    int e = (int)(idx >> 4);
    int c = (int)(idx & 15);    // chunk 0..15 -> floats [c*4, c*4+4)
    int h = c >> 2;
    int s = src[e];
    int d = dst[e];
    float alpha = g_ex[e * HEADS + h] / g_denom[d * HEADS + h];
    const float4 zv = *reinterpret_cast<const float4*>(&g_z[s * HF + c * 4]);
    float4 m4;
    m4.x = zv.x * alpha;
    m4.y = zv.y * alpha;
    m4.z = zv.z * alpha;
    m4.w = zv.w * alpha;
    float* p = &out[d * HF + c * 4];
    asm volatile("red.global.add.v4.f32 [%0], {%1,%2,%3,%4};"
                 :: "l"(p), "f"(m4.x), "f"(m4.y), "f"(m4.z), "f"(m4.w)
                 : "memory");
}

// ---------------------------------------------------------------------------
extern "C" void kernel_launch(void* const* d_in, const int* in_sizes, int n_in,
                              void* d_out, int out_size) {
    const float* feats  = (const float*)d_in[0];
    const float* W      = (const float*)d_in[1];
    const float* attn_l = (const float*)d_in[2];
    const float* attn_r = (const float*)d_in[3];
    const float* bias   = (const float*)d_in[4];
    const int*   src    = (const int*)d_in[5];
    const int*   dst    = (const int*)d_in[6];
    float* out = (float*)d_out;

    (void)in_sizes; (void)n_in; (void)out_size;

    // init: covers N_NODES*HF = 6.4M threads
    {
        int total = N_NODES * HF;
        k_init<<<(total + 255) / 256, 256>>>(out, bias);
    }
    // gemm: 4 nodes/block
    k_gemm<<<(N_NODES + 3) / 4, 256>>>(feats, W, attn_l, attn_r);
    // edge max / exp: E*HEADS threads
    {
        int total = N_EDGES * HEADS;
        k_edge_max<<<(total + 255) / 256, 256>>>(src, dst);
        k_edge_exp<<<(total + 255) / 256, 256>>>(src, dst);
    }
    // aggregate: E*16 threads
    {
        long long total = (long long)N_EDGES * 16;
        int blocks = (int)((total + 255) / 256);
        k_aggregate<<<blocks, 256>>>(src, dst, out);
    }
}

// round 2
// speedup vs baseline: 1.0843x; 1.0843x over previous
#include <cuda_runtime.h>
#include <cuda_bf16.h>
#include <math_constants.h>

#define N_NODES 100000
#define N_EDGES 1600000
#define IN_F    128
#define HEADS   4
#define OUT_F   16
#define HF      (HEADS * OUT_F)      // 64
#define NEG_SLOPE 0.2f

// Scratch (__device__ globals; no runtime allocation)
__device__ float g_z[N_NODES * HF];          // 25.6 MB projected features
__device__ float g_el[N_NODES * HEADS];
__device__ float g_er[N_NODES * HEADS];
__device__ int   g_cnt[N_NODES];             // histogram, then scatter cursor
__device__ int   g_off[N_NODES + 1];         // CSR row offsets (by dst)
__device__ int   g_srt_src[N_EDGES];         // src node per edge, grouped by dst

__device__ __forceinline__ float leaky_relu(float x) {
    return x > 0.0f ? x : NEG_SLOPE * x;
}

// ---------------------------------------------------------------------------
// Kernel 1: z = feats @ W^T ; el/er = <z, attn_l/r> per head.
// Also zeroes g_cnt (covered by the first 100000 global threads).
// Block: 256 threads, 4 nodes/block.
// ---------------------------------------------------------------------------
__global__ void k_gemm(const float* __restrict__ feats,
                       const float* __restrict__ W,
                       const float* __restrict__ attn_l,
                       const float* __restrict__ attn_r) {
    __shared__ float Wsm[IN_F][HF + 1];   // [k][col], padded
    __shared__ float fsm[4][IN_F];

    int tid = threadIdx.x;
    int gtid = blockIdx.x * 256 + tid;
    if (gtid < N_NODES) g_cnt[gtid] = 0;  // zero histogram for this call

    for (int i = tid; i < HF * IN_F; i += 256) {
        int col = i >> 7;
        int k   = i & (IN_F - 1);
        Wsm[k][col] = W[i];
    }
    int base_node = blockIdx.x * 4;
    for (int i = tid; i < 4 * IN_F; i += 256) {
        int nl = i >> 7;
        int k  = i & (IN_F - 1);
        fsm[nl][k] = feats[(base_node + nl) * IN_F + k];
    }
    __syncthreads();

    int nl   = tid >> 6;
    int col  = tid & (HF - 1);
    int node = base_node + nl;
    if (node >= N_NODES) return;

    float acc = 0.0f;
#pragma unroll
    for (int k = 0; k < IN_F; k++) {
        acc = fmaf(fsm[nl][k], Wsm[k][col], acc);
    }
    g_z[node * HF + col] = acc;

    int h = col >> 4;
    int f = col & 15;
    float vl = acc * attn_l[col];
    float vr = acc * attn_r[col];
#pragma unroll
    for (int off = 8; off >= 1; off >>= 1) {
        vl += __shfl_down_sync(0xffffffffu, vl, off, 16);
        vr += __shfl_down_sync(0xffffffffu, vr, off, 16);
    }
    if (f == 0) {
        g_el[node * HEADS + h] = vl;
        g_er[node * HEADS + h] = vr;
    }
}

// ---------------------------------------------------------------------------
// Kernel 2: histogram of dst
// ---------------------------------------------------------------------------
__global__ void k_hist(const int* __restrict__ dst) {
    int e = blockIdx.x * blockDim.x + threadIdx.x;
    if (e < N_EDGES) atomicAdd(&g_cnt[dst[e]], 1);
}

// ---------------------------------------------------------------------------
// Kernel 3: exclusive scan over g_cnt -> g_off (and cursor copy back to g_cnt)
// Single block, 1024 threads, chunked.
// ---------------------------------------------------------------------------
__global__ void k_scan() {
    __shared__ int warp_sums[32];
    __shared__ int s_carry;
    __shared__ int s_tot;
    int tid  = threadIdx.x;
    int lane = tid & 31;
    int wid  = tid >> 5;
    if (tid == 0) s_carry = 0;
    __syncthreads();

    for (int base = 0; base < N_NODES; base += 1024) {
        int i = base + tid;
        int v = (i < N_NODES) ? g_cnt[i] : 0;
        // inclusive warp scan
        int x = v;
#pragma unroll
        for (int o = 1; o < 32; o <<= 1) {
            int y = __shfl_up_sync(0xffffffffu, x, o);
            if (lane >= o) x += y;
        }
        if (lane == 31) warp_sums[wid] = x;
        __syncthreads();
        if (wid == 0) {
            int ws = warp_sums[lane];
            int xs = ws;
#pragma unroll
            for (int o = 1; o < 32; o <<= 1) {
                int y = __shfl_up_sync(0xffffffffu, xs, o);
                if (lane >= o) xs += y;
            }
            warp_sums[lane] = xs - ws;   // exclusive warp offsets
        }
        __syncthreads();
        int excl = x - v + warp_sums[wid] + s_carry;
        if (i < N_NODES) {
            g_off[i] = excl;
            g_cnt[i] = excl;   // scatter cursor
        }
        if (tid == 1023) s_tot = excl + v;   // carry for next chunk
        __syncthreads();
        if (tid == 0) s_carry = s_tot;
        __syncthreads();
    }
    if (tid == 0) g_off[N_NODES] = N_EDGES;
}

// ---------------------------------------------------------------------------
// Kernel 4: scatter src indices into dst-grouped order
// ---------------------------------------------------------------------------
__global__ void k_scatter(const int* __restrict__ src, const int* __restrict__ dst) {
    int e = blockIdx.x * blockDim.x + threadIdx.x;
    if (e >= N_EDGES) return;
    int d = dst[e];
    int pos = atomicAdd(&g_cnt[d], 1);
    g_srt_src[pos] = src[e];
}

// ---------------------------------------------------------------------------
// Kernel 5: fused softmax + aggregation. One warp per dst node.
// Lane owns output cols [2*lane, 2*lane+1]; head h = lane>>3.
// Single pass: num += ex * z[src], den += ex; out = num/den + bias.
// ---------------------------------------------------------------------------
__global__ void k_agg(const float* __restrict__ bias, float* __restrict__ out) {
    int gwarp = (blockIdx.x * blockDim.x + threadIdx.x) >> 5;
    int lane  = threadIdx.x & 31;
    if (gwarp >= N_NODES) return;
    int d = gwarp;

    int beg = g_off[d];
    int end = g_off[d + 1];

    int h = lane >> 3;                       // head of this lane's columns
    float er_h = g_er[d * HEADS + h];

    float2 num = make_float2(0.0f, 0.0f);
    float  den = 0.0f;

    for (int i = beg; i < end; i++) {
        int s = g_srt_src[i];                           // warp-uniform
        float el_h = g_el[s * HEADS + h];
        float e = leaky_relu(el_h + er_h);
        float ex = __expf(e);
        const float2 zv = *reinterpret_cast<const float2*>(&g_z[s * HF + 2 * lane]);
        num.x = fmaf(ex, zv.x, num.x);
        num.y = fmaf(ex, zv.y, num.y);
        den += ex;                                      // identical across the 8 lanes of a head
    }

    float inv = (den > 0.0f) ? __frcp_rn(den) : 0.0f;   // empty segment -> out = bias
    const float2 b2 = *reinterpret_cast<const float2*>(&bias[2 * lane]);
    float2 o;
    o.x = num.x * inv + b2.x;
    o.y = num.y * inv + b2.y;
    *reinterpret_cast<float2*>(&out[d * HF + 2 * lane]) = o;
}

// ---------------------------------------------------------------------------
extern "C" void kernel_launch(void* const* d_in, const int* in_sizes, int n_in,
                              void* d_out, int out_size) {
    const float* feats  = (const float*)d_in[0];
    const float* W      = (const float*)d_in[1];
    const float* attn_l = (const float*)d_in[2];
    const float* attn_r = (const float*)d_in[3];
    const float* bias   = (const float*)d_in[4];
    const int*   src    = (const int*)d_in[5];
    const int*   dst    = (const int*)d_in[6];
    float* out = (float*)d_out;

    (void)in_sizes; (void)n_in; (void)out_size;

    k_gemm<<<(N_NODES + 3) / 4, 256>>>(feats, W, attn_l, attn_r);
    k_hist<<<(N_EDGES + 255) / 256, 256>>>(dst);
    k_scan<<<1, 1024>>>();
    k_scatter<<<(N_EDGES + 255) / 256, 256>>>(src, dst);
    // 100000 warps, 8 warps/block
    k_agg<<<(N_NODES + 7) / 8, 256>>>(bias, out);
}

// round 3
// speedup vs baseline: 2.2720x; 2.0954x over previous
#include <cuda_runtime.h>
#include <cuda_bf16.h>

#define N_NODES 100000
#define N_EDGES 1600000
#define IN_F    128
#define HEADS   4
#define HF      64
#define NEG_SLOPE 0.2f
#define NB_SCAN 98          // ceil(N_NODES / 1024)

// Scratch (__device__ globals; no runtime allocation)
__device__ float g_z[N_NODES * HF];          // 25.6 MB projected features
__device__ float g_el[N_NODES * HEADS];
__device__ float g_er[N_NODES * HEADS];
__device__ int   g_cnt[N_NODES];             // histogram -> scatter cursor
__device__ int   g_off[N_NODES + 1];         // CSR offsets by dst
__device__ int   g_bsum[128];
__device__ int   g_bbase[128];
__device__ int   g_srt_src[N_EDGES];         // src per edge, grouped by dst
__device__ float g_srt_ex[N_EDGES * HEADS];  // exp(logit) per edge*head, grouped

__device__ __forceinline__ float lrelu(float x) {
    return x > 0.0f ? x : NEG_SLOPE * x;
}

// ---------------------------------------------------------------------------
// GEMM: z = feats @ W^T, el/er = <z, attn>. 64 nodes/block, 256 thr, 4x4 tile.
// Also zeroes g_cnt.
// ---------------------------------------------------------------------------
__global__ __launch_bounds__(256) void k_gemm(const float* __restrict__ feats,
                                              const float* __restrict__ W,
                                              const float* __restrict__ attn_l,
                                              const float* __restrict__ attn_r) {
    __shared__ float fsmT[64][68];   // [k][node], padded (conflict-free transpose)
    __shared__ float Wsm[64][68];    // [k][col]

    int tid = threadIdx.x;
    int gtid = blockIdx.x * 256 + tid;
    if (gtid < N_NODES) g_cnt[gtid] = 0;

    int bn = blockIdx.x * 64;
    int ng = tid >> 4;      // 0..15 -> 4 nodes each
    int cg = tid & 15;      // 0..15 -> 4 cols each

    float acc[4][4];
#pragma unroll
    for (int i = 0; i < 4; i++)
#pragma unroll
        for (int j = 0; j < 4; j++) acc[i][j] = 0.0f;

#pragma unroll
    for (int p = 0; p < 2; p++) {
        int k0 = p * 64;
        if (p) __syncthreads();
        // stage feats tile transposed: fsmT[kk][node]
#pragma unroll
        for (int idx = tid; idx < 4096; idx += 256) {
            int node = idx >> 6;
            int kk   = idx & 63;
            float v = 0.0f;
            if (bn + node < N_NODES) v = feats[(bn + node) * IN_F + k0 + kk];
            fsmT[kk][node] = v;
        }
        // stage W tile transposed: Wsm[kk][col]
#pragma unroll
        for (int idx = tid; idx < 4096; idx += 256) {
            int col = idx >> 6;
            int kk  = idx & 63;
            Wsm[kk][col] = W[col * IN_F + k0 + kk];
        }
        __syncthreads();

#pragma unroll 8
        for (int kk = 0; kk < 64; kk++) {
            float4 f4 = *(const float4*)&fsmT[kk][ng * 4];
            float4 w4 = *(const float4*)&Wsm[kk][cg * 4];
            float fa[4] = {f4.x, f4.y, f4.z, f4.w};
            float wa[4] = {w4.x, w4.y, w4.z, w4.w};
#pragma unroll
            for (int i = 0; i < 4; i++)
#pragma unroll
                for (int j = 0; j < 4; j++)
                    acc[i][j] = fmaf(fa[i], wa[j], acc[i][j]);
        }
    }

    // epilogue: write z rows + head-reduced el/er
    int h = cg >> 2;
    float al[4], ar[4];
#pragma unroll
    for (int j = 0; j < 4; j++) {
        al[j] = attn_l[cg * 4 + j];
        ar[j] = attn_r[cg * 4 + j];
    }
#pragma unroll
    for (int i = 0; i < 4; i++) {
        int node = bn + ng * 4 + i;
        float vl = acc[i][0] * al[0] + acc[i][1] * al[1] +
                   acc[i][2] * al[2] + acc[i][3] * al[3];
        float vr = acc[i][0] * ar[0] + acc[i][1] * ar[1] +
                   acc[i][2] * ar[2] + acc[i][3] * ar[3];
        // reduce across the 4 cg-lanes of this head (lanes differ in bits 0-1)
        vl += __shfl_xor_sync(0xffffffffu, vl, 1);
        vl += __shfl_xor_sync(0xffffffffu, vl, 2);
        vr += __shfl_xor_sync(0xffffffffu, vr, 1);
        vr += __shfl_xor_sync(0xffffffffu, vr, 2);
        if (node < N_NODES) {
            float4 zr = make_float4(acc[i][0], acc[i][1], acc[i][2], acc[i][3]);
            *(float4*)&g_z[node * HF + cg * 4] = zr;
            if ((cg & 3) == 0) {
                g_el[node * HEADS + h] = vl;
                g_er[node * HEADS + h] = vr;
            }
        }
    }
}

// ---------------------------------------------------------------------------
// Histogram of dst (4 edges/thread, vectorized index load)
// ---------------------------------------------------------------------------
__global__ void k_hist(const int* __restrict__ dst) {
    int t = blockIdx.x * blockDim.x + threadIdx.x;
    int base = t * 4;
    if (base >= N_EDGES) return;
    int4 d4 = *(const int4*)&dst[base];   // N_EDGES % 4 == 0
    atomicAdd(&g_cnt[d4.x], 1);
    atomicAdd(&g_cnt[d4.y], 1);
    atomicAdd(&g_cnt[d4.z], 1);
    atomicAdd(&g_cnt[d4.w], 1);
}

// ---------------------------------------------------------------------------
// Scan phase 1: per-block (1024) exclusive scan, block totals to g_bsum
// ---------------------------------------------------------------------------
__global__ __launch_bounds__(1024) void k_scan1() {
    __shared__ int wsum[32];
    int tid  = threadIdx.x;
    int lane = tid & 31;
    int wid  = tid >> 5;
    int i = blockIdx.x * 1024 + tid;
    int v = (i < N_NODES) ? g_cnt[i] : 0;
    int x = v;
#pragma unroll
    for (int o = 1; o < 32; o <<= 1) {
        int y = __shfl_up_sync(0xffffffffu, x, o);
        if (lane >= o) x += y;
    }
    if (lane == 31) wsum[wid] = x;
    __syncthreads();
    if (wid == 0) {
        int wv = wsum[lane];
        int xs = wv;
#pragma unroll
        for (int o = 1; o < 32; o <<= 1) {
            int y = __shfl_up_sync(0xffffffffu, xs, o);
            if (lane >= o) xs += y;
        }
        wsum[lane] = xs - wv;
    }
    __syncthreads();
    int excl = x - v + wsum[wid];
    if (i < N_NODES) g_off[i] = excl;
    if (tid == 1023) g_bsum[blockIdx.x] = excl + v;
}

// ---------------------------------------------------------------------------
// Scan phase 2: exclusive scan of NB_SCAN block sums (1 warp)
// ---------------------------------------------------------------------------
__global__ void k_scan2() {
    int lane = threadIdx.x;
    int carry = 0;
#pragma unroll
    for (int c = 0; c < (NB_SCAN + 31) / 32; c++) {
        int i = c * 32 + lane;
        int v = (i < NB_SCAN) ? g_bsum[i] : 0;
        int x = v;
#pragma unroll
        for (int o = 1; o < 32; o <<= 1) {
            int y = __shfl_up_sync(0xffffffffu, x, o);
            if (lane >= o) x += y;
        }
        if (i < NB_SCAN) g_bbase[i] = carry + x - v;
        carry += __shfl_sync(0xffffffffu, x, 31);
    }
}

// ---------------------------------------------------------------------------
// Scan phase 3: add block bases; init cursor
// ---------------------------------------------------------------------------
__global__ __launch_bounds__(1024) void k_scan3() {
    int i = blockIdx.x * 1024 + threadIdx.x;
    if (i < N_NODES) {
        int o = g_off[i] + g_bbase[blockIdx.x];
        g_off[i] = o;
        g_cnt[i] = o;
    }
    if (i == 0) g_off[N_NODES] = N_EDGES;
}

// ---------------------------------------------------------------------------
// Scatter: group edges by dst; precompute ex = exp(leaky(el[s]+er[d])) per head
// ---------------------------------------------------------------------------
__global__ void k_scatter(const int* __restrict__ src, const int* __restrict__ dst) {
    int e = blockIdx.x * blockDim.x + threadIdx.x;
    if (e >= N_EDGES) return;
    int s = src[e];
    int d = dst[e];
    int pos = atomicAdd(&g_cnt[d], 1);
    float4 el4 = *(const float4*)&g_el[s * HEADS];
    float4 er4 = *(const float4*)&g_er[d * HEADS];
    float4 ex;
    ex.x = __expf(lrelu(el4.x + er4.x));
    ex.y = __expf(lrelu(el4.y + er4.y));
    ex.z = __expf(lrelu(el4.z + er4.z));
    ex.w = __expf(lrelu(el4.w + er4.w));
    g_srt_src[pos] = s;
    *(float4*)&g_srt_ex[pos * 4] = ex;
}

// ---------------------------------------------------------------------------
// Aggregate: one warp per dst node, software-pipelined gather.
// Lane owns cols [2*lane, 2*lane+1]; head h = lane>>3.
// ---------------------------------------------------------------------------
__global__ void k_agg(const float* __restrict__ bias, float* __restrict__ out) {
    int gwarp = (blockIdx.x * blockDim.x + threadIdx.x) >> 5;
    int lane  = threadIdx.x & 31;
    if (gwarp >= N_NODES) return;
    int d = gwarp;
    int h = lane >> 3;

    int i    = g_off[d];
    int nrem = g_off[d + 1] - i;

    float2 num = make_float2(0.0f, 0.0f);
    float  den = 0.0f;

    int   sA = 0, sB = 0;
    float exA = 0.0f, exB = 0.0f;
    if (nrem > 0) { sA = g_srt_src[i];     exA = g_srt_ex[4 * i + h]; }
    if (nrem > 1) { sB = g_srt_src[i + 1]; exB = g_srt_ex[4 * (i + 1) + h]; }

    while (nrem >= 2) {
        float2 zA = *(const float2*)&g_z[sA * HF + 2 * lane];
        float2 zB = *(const float2*)&g_z[sB * HF + 2 * lane];
        float eA = exA, eB = exB;
        int i2 = i + 2;
        if (nrem > 2) { sA = g_srt_src[i2];     exA = g_srt_ex[4 * i2 + h]; }
        if (nrem > 3) { sB = g_srt_src[i2 + 1]; exB = g_srt_ex[4 * (i2 + 1) + h]; }
        num.x = fmaf(eA, zA.x, num.x);
        num.y = fmaf(eA, zA.y, num.y);
        num.x = fmaf(eB, zB.x, num.x);
        num.y = fmaf(eB, zB.y, num.y);
        den += eA + eB;
        i = i2;
        nrem -= 2;
    }
    if (nrem == 1) {
        float2 zA = *(const float2*)&g_z[sA * HF + 2 * lane];
        num.x = fmaf(exA, zA.x, num.x);
        num.y = fmaf(exA, zA.y, num.y);
        den += exA;
    }

    float inv = (den > 0.0f) ? __frcp_rn(den) : 0.0f;  // empty segment -> bias
    const float2 b2 = *(const float2*)&bias[2 * lane];
    float2 o;
    o.x = num.x * inv + b2.x;
    o.y = num.y * inv + b2.y;
    *(float2*)&out[d * HF + 2 * lane] = o;
}

// ---------------------------------------------------------------------------
extern "C" void kernel_launch(void* const* d_in, const int* in_sizes, int n_in,
                              void* d_out, int out_size) {
    const float* feats  = (const float*)d_in[0];
    const float* W      = (const float*)d_in[1];
    const float* attn_l = (const float*)d_in[2];
    const float* attn_r = (const float*)d_in[3];
    const float* bias   = (const float*)d_in[4];
    const int*   src    = (const int*)d_in[5];
    const int*   dst    = (const int*)d_in[6];
    float* out = (float*)d_out;

    (void)in_sizes; (void)n_in; (void)out_size;

    k_gemm<<<(N_NODES + 63) / 64, 256>>>(feats, W, attn_l, attn_r);
    k_hist<<<(N_EDGES / 4 + 255) / 256, 256>>>(dst);
    k_scan1<<<NB_SCAN, 1024>>>();
    k_scan2<<<1, 32>>>();
    k_scan3<<<NB_SCAN, 1024>>>();
    k_scatter<<<(N_EDGES + 255) / 256, 256>>>(src, dst);
    k_agg<<<(N_NODES + 7) / 8, 256>>>(bias, out);
}

// round 4
// speedup vs baseline: 2.3846x; 1.0496x over previous
#include <cuda_runtime.h>
#include <cuda_bf16.h>

#define N_NODES 100000
#define N_EDGES 1600000
#define IN_F    128
#define HEADS   4
#define HF      64
#define NEG_SLOPE 0.2f
#define NB_SCAN 98          // ceil(N_NODES / 1024)

// Scratch (__device__ globals; no runtime allocation)
__device__ float g_z[N_NODES * HF];          // 25.6 MB projected features
__device__ float g_el[N_NODES * HEADS];
__device__ float g_er[N_NODES * HEADS];
__device__ int   g_cnt[N_NODES];             // histogram -> scatter cursor
__device__ int   g_off[N_NODES + 1];         // CSR offsets by dst
__device__ int   g_bsum[128];
__device__ int   g_srt_src[N_EDGES];         // src per edge, grouped by dst
__device__ float g_srt_ex[N_EDGES * HEADS];  // exp(logit) per edge*head, grouped

__device__ __forceinline__ float lrelu(float x) {
    return x > 0.0f ? x : NEG_SLOPE * x;
}

// --- packed f32x2 helpers (sm_103a FFMA2 path; ptxas won't auto-fuse) ------
__device__ __forceinline__ unsigned long long pack2(float a, float b) {
    unsigned long long r;
    asm("mov.b64 %0, {%1, %2};" : "=l"(r) : "f"(a), "f"(b));
    return r;
}
__device__ __forceinline__ void ffma2(unsigned long long& d,
                                      unsigned long long a,
                                      unsigned long long b) {
    asm("fma.rn.f32x2 %0, %1, %2, %0;" : "+l"(d) : "l"(a), "l"(b));
}
__device__ __forceinline__ float2 unpack2(unsigned long long v) {
    float lo, hi;
    asm("mov.b64 {%0, %1}, %2;" : "=f"(lo), "=f"(hi) : "l"(v));
    return make_float2(lo, hi);
}

// ---------------------------------------------------------------------------
// GEMM: z = feats @ W^T, el/er = <z, attn>. 64 nodes/block, 256 thr,
// 4x4 register tile computed as 8 packed FFMA2 per k. Also zeroes g_cnt.
// ---------------------------------------------------------------------------
__global__ __launch_bounds__(256) void k_gemm(const float* __restrict__ feats,
                                              const float* __restrict__ W,
                                              const float* __restrict__ attn_l,
                                              const float* __restrict__ attn_r) {
    __shared__ float fsmT[64][68];   // [k][node], padded
    __shared__ float Wsm[64][68];    // [k][col]

    int tid = threadIdx.x;
    int gtid = blockIdx.x * 256 + tid;
    if (gtid < N_NODES) g_cnt[gtid] = 0;

    int bn = blockIdx.x * 64;
    int ng = tid >> 4;      // 0..15 -> 4 nodes
    int cg = tid & 15;      // 0..15 -> 4 cols

    unsigned long long acc2[4][2];   // [node][col-pair]
#pragma unroll
    for (int i = 0; i < 4; i++) { acc2[i][0] = 0ull; acc2[i][1] = 0ull; }

#pragma unroll
    for (int p = 0; p < 2; p++) {
        int k0 = p * 64;
        if (p) __syncthreads();
#pragma unroll
        for (int idx = tid; idx < 4096; idx += 256) {
            int node = idx >> 6;
            int kk   = idx & 63;
            float v = 0.0f;
            if (bn + node < N_NODES) v = feats[(bn + node) * IN_F + k0 + kk];
            fsmT[kk][node] = v;
        }
#pragma unroll
        for (int idx = tid; idx < 4096; idx += 256) {
            int col = idx >> 6;
            int kk  = idx & 63;
            Wsm[kk][col] = W[col * IN_F + k0 + kk];
        }
        __syncthreads();

#pragma unroll 8
        for (int kk = 0; kk < 64; kk++) {
            float4 f4 = *(const float4*)&fsmT[kk][ng * 4];
            float4 w4 = *(const float4*)&Wsm[kk][cg * 4];
            unsigned long long wA = pack2(w4.x, w4.y);
            unsigned long long wB = pack2(w4.z, w4.w);
            unsigned long long b0 = pack2(f4.x, f4.x);
            unsigned long long b1 = pack2(f4.y, f4.y);
            unsigned long long b2 = pack2(f4.z, f4.z);
            unsigned long long b3 = pack2(f4.w, f4.w);
            ffma2(acc2[0][0], b0, wA); ffma2(acc2[0][1], b0, wB);
            ffma2(acc2[1][0], b1, wA); ffma2(acc2[1][1], b1, wB);
            ffma2(acc2[2][0], b2, wA); ffma2(acc2[2][1], b2, wB);
            ffma2(acc2[3][0], b3, wA); ffma2(acc2[3][1], b3, wB);
        }
    }

    // epilogue
    int h = cg >> 2;
    float al[4], ar[4];
#pragma unroll
    for (int j = 0; j < 4; j++) {
        al[j] = attn_l[cg * 4 + j];
        ar[j] = attn_r[cg * 4 + j];
    }
#pragma unroll
    for (int i = 0; i < 4; i++) {
        int node = bn + ng * 4 + i;
        float2 a01 = unpack2(acc2[i][0]);
        float2 a23 = unpack2(acc2[i][1]);
        float acc0 = a01.x, acc1 = a01.y, acc2f = a23.x, acc3 = a23.y;
        float vl = acc0 * al[0] + acc1 * al[1] + acc2f * al[2] + acc3 * al[3];
        float vr = acc0 * ar[0] + acc1 * ar[1] + acc2f * ar[2] + acc3 * ar[3];
        vl += __shfl_xor_sync(0xffffffffu, vl, 1);
        vl += __shfl_xor_sync(0xffffffffu, vl, 2);
        vr += __shfl_xor_sync(0xffffffffu, vr, 1);
        vr += __shfl_xor_sync(0xffffffffu, vr, 2);
        if (node < N_NODES) {
            *(float4*)&g_z[node * HF + cg * 4] = make_float4(acc0, acc1, acc2f, acc3);
            if ((cg & 3) == 0) {
                g_el[node * HEADS + h] = vl;
                g_er[node * HEADS + h] = vr;
            }
        }
    }
}

// ---------------------------------------------------------------------------
// Histogram of dst (4 edges/thread)
// ---------------------------------------------------------------------------
__global__ void k_hist(const int* __restrict__ dst) {
    int t = blockIdx.x * blockDim.x + threadIdx.x;
    int base = t * 4;
    if (base >= N_EDGES) return;
    int4 d4 = *(const int4*)&dst[base];
    atomicAdd(&g_cnt[d4.x], 1);
    atomicAdd(&g_cnt[d4.y], 1);
    atomicAdd(&g_cnt[d4.z], 1);
    atomicAdd(&g_cnt[d4.w], 1);
}

// ---------------------------------------------------------------------------
// Scan phase 1: per-block (1024) exclusive scan, block totals to g_bsum
// ---------------------------------------------------------------------------
__global__ __launch_bounds__(1024) void k_scan1() {
    __shared__ int wsum[32];
    int tid  = threadIdx.x;
    int lane = tid & 31;
    int wid  = tid >> 5;
    int i = blockIdx.x * 1024 + tid;
    int v = (i < N_NODES) ? g_cnt[i] : 0;
    int x = v;
#pragma unroll
    for (int o = 1; o < 32; o <<= 1) {
        int y = __shfl_up_sync(0xffffffffu, x, o);
        if (lane >= o) x += y;
    }
    if (lane == 31) wsum[wid] = x;
    __syncthreads();
    if (wid == 0) {
        int wv = wsum[lane];
        int xs = wv;
#pragma unroll
        for (int o = 1; o < 32; o <<= 1) {
            int y = __shfl_up_sync(0xffffffffu, xs, o);
            if (lane >= o) xs += y;
        }
        wsum[lane] = xs - wv;
    }
    __syncthreads();
    int excl = x - v + wsum[wid];
    if (i < N_NODES) g_off[i] = excl;
    if (tid == 1023) g_bsum[blockIdx.x] = excl + v;
}

// ---------------------------------------------------------------------------
// Scan phase 2+3 fused: each block computes its own base from g_bsum,
// adds it, initializes cursor.
// ---------------------------------------------------------------------------
__global__ __launch_bounds__(1024) void k_scan3() {
    __shared__ int s_base;
    int tid = threadIdx.x;
    if (tid < 32) {
        int acc = 0;
        for (int j = tid; j < NB_SCAN; j += 32)
            if (j < (int)blockIdx.x) acc += g_bsum[j];
#pragma unroll
        for (int o = 16; o >= 1; o >>= 1)
            acc += __shfl_xor_sync(0xffffffffu, acc, o);
        if (tid == 0) s_base = acc;
    }
    __syncthreads();
    int i = blockIdx.x * 1024 + tid;
    if (i < N_NODES) {
        int o = g_off[i] + s_base;
        g_off[i] = o;
        g_cnt[i] = o;
    }
    if (i == 0) g_off[N_NODES] = N_EDGES;
}

// ---------------------------------------------------------------------------
// Scatter: 2 edges/thread; group edges by dst, precompute per-head ex
// ---------------------------------------------------------------------------
__global__ void k_scatter(const int* __restrict__ src, const int* __restrict__ dst) {
    int t = blockIdx.x * blockDim.x + threadIdx.x;
    int e = t * 2;
    if (e >= N_EDGES) return;
    int2 s2 = *(const int2*)&src[e];
    int2 d2 = *(const int2*)&dst[e];

    int pos0 = atomicAdd(&g_cnt[d2.x], 1);
    float4 el4 = *(const float4*)&g_el[s2.x * HEADS];
    float4 er4 = *(const float4*)&g_er[d2.x * HEADS];
    float4 ex0;
    ex0.x = __expf(lrelu(el4.x + er4.x));
    ex0.y = __expf(lrelu(el4.y + er4.y));
    ex0.z = __expf(lrelu(el4.z + er4.z));
    ex0.w = __expf(lrelu(el4.w + er4.w));
    g_srt_src[pos0] = s2.x;
    *(float4*)&g_srt_ex[pos0 * 4] = ex0;

    int pos1 = atomicAdd(&g_cnt[d2.y], 1);
    float4 el4b = *(const float4*)&g_el[s2.y * HEADS];
    float4 er4b = *(const float4*)&g_er[d2.y * HEADS];
    float4 ex1;
    ex1.x = __expf(lrelu(el4b.x + er4b.x));
    ex1.y = __expf(lrelu(el4b.y + er4b.y));
    ex1.z = __expf(lrelu(el4b.z + er4b.z));
    ex1.w = __expf(lrelu(el4b.w + er4b.w));
    g_srt_src[pos1] = s2.y;
    *(float4*)&g_srt_ex[pos1 * 4] = ex1;
}

// ---------------------------------------------------------------------------
// Aggregate: one warp per dst node, software-pipelined gather.
// ---------------------------------------------------------------------------
__global__ void k_agg(const float* __restrict__ bias, float* __restrict__ out) {
    int gwarp = (blockIdx.x * blockDim.x + threadIdx.x) >> 5;
    int lane  = threadIdx.x & 31;
    if (gwarp >= N_NODES) return;
    int d = gwarp;
    int h = lane >> 3;

    int i    = g_off[d];
    int nrem = g_off[d + 1] - i;

    float2 num = make_float2(0.0f, 0.0f);
    float  den = 0.0f;

    int   sA = 0, sB = 0;
    float exA = 0.0f, exB = 0.0f;
    if (nrem > 0) { sA = g_srt_src[i];     exA = g_srt_ex[4 * i + h]; }
    if (nrem > 1) { sB = g_srt_src[i + 1]; exB = g_srt_ex[4 * (i + 1) + h]; }

    while (nrem >= 2) {
        float2 zA = *(const float2*)&g_z[sA * HF + 2 * lane];
        float2 zB = *(const float2*)&g_z[sB * HF + 2 * lane];
        float eA = exA, eB = exB;
        int i2 = i + 2;
        if (nrem > 2) { sA = g_srt_src[i2];     exA = g_srt_ex[4 * i2 + h]; }
        if (nrem > 3) { sB = g_srt_src[i2 + 1]; exB = g_srt_ex[4 * (i2 + 1) + h]; }
        num.x = fmaf(eA, zA.x, num.x);
        num.y = fmaf(eA, zA.y, num.y);
        num.x = fmaf(eB, zB.x, num.x);
        num.y = fmaf(eB, zB.y, num.y);
        den += eA + eB;
        i = i2;
        nrem -= 2;
    }
    if (nrem == 1) {
        float2 zA = *(const float2*)&g_z[sA * HF + 2 * lane];
        num.x = fmaf(exA, zA.x, num.x);
        num.y = fmaf(exA, zA.y, num.y);
        den += exA;
    }

    float inv = (den > 0.0f) ? __frcp_rn(den) : 0.0f;
    const float2 b2 = *(const float2*)&bias[2 * lane];
    float2 o;
    o.x = num.x * inv + b2.x;
    o.y = num.y * inv + b2.y;
    *(float2*)&out[d * HF + 2 * lane] = o;
}

// ---------------------------------------------------------------------------
extern "C" void kernel_launch(void* const* d_in, const int* in_sizes, int n_in,
                              void* d_out, int out_size) {
    const float* feats  = (const float*)d_in[0];
    const float* W      = (const float*)d_in[1];
    const float* attn_l = (const float*)d_in[2];
    const float* attn_r = (const float*)d_in[3];
    const float* bias   = (const float*)d_in[4];
    const int*   src    = (const int*)d_in[5];
    const int*   dst    = (const int*)d_in[6];
    float* out = (float*)d_out;

    (void)in_sizes; (void)n_in; (void)out_size;

    k_gemm<<<(N_NODES + 63) / 64, 256>>>(feats, W, attn_l, attn_r);
    k_hist<<<(N_EDGES / 4 + 255) / 256, 256>>>(dst);
    k_scan1<<<NB_SCAN, 1024>>>();
    k_scan3<<<NB_SCAN, 1024>>>();
    k_scatter<<<(N_EDGES / 2 + 255) / 256, 256>>>(src, dst);
    k_agg<<<(N_NODES + 7) / 8, 256>>>(bias, out);
}